// round 14
// baseline (speedup 1.0000x reference)
#include <cuda_runtime.h>
#include <math.h>

#define BATCH 512
#define HO 31
#define WO 31
#define HW 64
#define PLANE (HO * WO)          // 961
#define OUTB (12 * PLANE)        // 11532
#define RSTRIDE 962              // padded res slab stride (962*8 bytes % 16 == 0)

// Closed-form reduction (verified R1..R13):
//   per patch: S2=sum p_i^2 ; D2 signed sum (rows +,-,+,-; cols +,-,-,+)
//   dP = pairs (i, i^12) = rows 0*3 + 1*2 per column
//   out[plane] = cA[plane]*(D2/S2) + cB[plane]*(dP/S2); coefs from U3 of qubit 0.
//
// K1: horizontal-pair threads -> (Dl,dd) per patch into scratch (LDG.128 loads).
// K2: output-driven; plane p's aligned float4 chunks start at a_p=(-p) mod 4 so
//     961p + a_p == 0 (mod 4): every store is an aligned STG.128.

__device__ float2 g_res[BATCH * RSTRIDE];   // 3.94 MB scratch (static, allowed)

__global__ __launch_bounds__(256) void k1_invariants(const float* __restrict__ x) {
    const int t = threadIdx.x;                    // 0..15 -> patch pair (2t, 2t+1)
    const int ho = blockIdx.x * 16 + threadIdx.y;
    const int b = blockIdx.y;
    if (ho >= HO) return;
    const bool hasB = (t < 15);                   // wo=2t+1=31 doesn't exist at t=15

    // pair uses input cols 4t..4t+5 of rows 2ho..2ho+3 (LDG.128 + LDG.64, aligned)
    const float* base = x + (size_t)b * (HW * HW) + (size_t)(2 * ho) * HW + 4 * t;
    float4 a0 = *reinterpret_cast<const float4*>(base);
    float4 a1 = *reinterpret_cast<const float4*>(base + HW);
    float4 a2 = *reinterpret_cast<const float4*>(base + 2 * HW);
    float4 a3 = *reinterpret_cast<const float4*>(base + 3 * HW);
    float2 c0 = make_float2(0.f, 0.f), c1 = c0, c2 = c0, c3 = c0;
    if (hasB) {
        c0 = *reinterpret_cast<const float2*>(base + 4);
        c1 = *reinterpret_cast<const float2*>(base + HW + 4);
        c2 = *reinterpret_cast<const float2*>(base + 2 * HW + 4);
        c3 = *reinterpret_cast<const float2*>(base + 3 * HW + 4);
    }

    float2* rp = g_res + (size_t)b * RSTRIDE + ho * WO + 2 * t;

    // ---- patch A: cols (a.x, a.y, a.z, a.w) ----
    {
        float s0 = a0.x * a0.x + a0.y * a0.y + a0.z * a0.z + a0.w * a0.w;
        float s1 = a1.x * a1.x + a1.y * a1.y + a1.z * a1.z + a1.w * a1.w;
        float s2 = a2.x * a2.x + a2.y * a2.y + a2.z * a2.z + a2.w * a2.w;
        float s3 = a3.x * a3.x + a3.y * a3.y + a3.z * a3.z + a3.w * a3.w;
        float d0 = a0.x * a0.x - a0.y * a0.y - a0.z * a0.z + a0.w * a0.w;
        float d1 = a1.x * a1.x - a1.y * a1.y - a1.z * a1.z + a1.w * a1.w;
        float d2 = a2.x * a2.x - a2.y * a2.y - a2.z * a2.z + a2.w * a2.w;
        float d3 = a3.x * a3.x - a3.y * a3.y - a3.z * a3.z + a3.w * a3.w;
        float S = s0 + s1 + s2 + s3;
        float D = d0 - d1 + d2 - d3;
        float P = a0.x * a3.x + a0.y * a3.y + a0.z * a3.z + a0.w * a3.w
                + a1.x * a2.x + a1.y * a2.y + a1.z * a2.z + a1.w * a2.w;
        float inv = 1.0f / S;
        rp[0] = make_float2(D * inv, P * inv);
    }

    // ---- patch B: cols (a.z, a.w, c.x, c.y) ----
    if (hasB) {
        float s0 = a0.z * a0.z + a0.w * a0.w + c0.x * c0.x + c0.y * c0.y;
        float s1 = a1.z * a1.z + a1.w * a1.w + c1.x * c1.x + c1.y * c1.y;
        float s2 = a2.z * a2.z + a2.w * a2.w + c2.x * c2.x + c2.y * c2.y;
        float s3 = a3.z * a3.z + a3.w * a3.w + c3.x * c3.x + c3.y * c3.y;
        float d0 = a0.z * a0.z - a0.w * a0.w - c0.x * c0.x + c0.y * c0.y;
        float d1 = a1.z * a1.z - a1.w * a1.w - c1.x * c1.x + c1.y * c1.y;
        float d2 = a2.z * a2.z - a2.w * a2.w - c2.x * c2.x + c2.y * c2.y;
        float d3 = a3.z * a3.z - a3.w * a3.w - c3.x * c3.x + c3.y * c3.y;
        float S = s0 + s1 + s2 + s3;
        float D = d0 - d1 + d2 - d3;
        float P = a0.z * a3.z + a0.w * a3.w + c0.x * c3.x + c0.y * c3.y
                + a1.z * a2.z + a1.w * a2.w + c1.x * c2.x + c1.y * c2.y;
        float inv = 1.0f / S;
        rp[1] = make_float2(D * inv, P * inv);
    }
}

__global__ __launch_bounds__(256) void k2_expand(const float* __restrict__ w,
                                                 float* __restrict__ out) {
    __shared__ float cA[12], cB[12];
    const int t = threadIdx.x;
    if (t < 4) {
        const int k = t;
        float th = w[k * 12 + 0], ph = w[k * 12 + 1], om = w[k * 12 + 2];
        float st, ct, spo, cpo, smp, cmp, sp, cp, som, com_;
        sincosf(th, &st, &ct);
        sincosf(ph, &sp, &cp);
        sincosf(ph + om, &spo, &cpo);
        sincosf(om - ph, &smp, &cmp);
        sincosf(om, &som, &com_);
        float cc = 0.5f * (1.0f + ct);
        float ss = 0.5f * (1.0f - ct);
        cA[3 * k + 0] = st * cp;                         // ex
        cB[3 * k + 0] = 2.0f * (cc * cpo - ss * cmp);
        cA[3 * k + 1] = st * sp;                         // ey
        cB[3 * k + 1] = 2.0f * (cc * spo + ss * smp);
        cA[3 * k + 2] = ct;                              // ez
        cB[3 * k + 2] = -2.0f * st * com_;
    }
    __syncthreads();

    const int b = blockIdx.x;
    const float2* rbase = g_res + (size_t)b * RSTRIDE;
    float* ob = out + (size_t)b * OUTB;

    if (t < 238) {
        // load res[4t .. 4t+7] with 4 aligned LDG.128 (covers all shifts a_p)
        const float4* rv = reinterpret_cast<const float4*>(rbase + 4 * t);
        float4 q0 = rv[0], q1 = rv[1], q2 = rv[2], q3 = rv[3];
        float2 r[8];
        r[0] = make_float2(q0.x, q0.y); r[1] = make_float2(q0.z, q0.w);
        r[2] = make_float2(q1.x, q1.y); r[3] = make_float2(q1.z, q1.w);
        r[4] = make_float2(q2.x, q2.y); r[5] = make_float2(q2.z, q2.w);
        r[6] = make_float2(q3.x, q3.y); r[7] = make_float2(q3.z, q3.w);

#pragma unroll
        for (int p = 0; p < 12; ++p) {
            const int ap = (4 - (p & 3)) & 3;            // (-p) mod 4 (compile-time)
            float a = cA[p], g = cB[p];
            float4 o;
            o.x = a * r[ap + 0].x + g * r[ap + 0].y;
            o.y = a * r[ap + 1].x + g * r[ap + 1].y;
            o.z = a * r[ap + 2].x + g * r[ap + 2].y;
            o.w = a * r[ap + 3].x + g * r[ap + 3].y;
            // 961p + ap == 0 (mod 4)  ->  aligned STG.128
            *reinterpret_cast<float4*>(ob + PLANE * p + ap + 4 * t) = o;
        }
    } else {
        // cleanup: per plane the 9 floats not covered by fast chunks
        // plane-local { 0..ap-1 } U { ap+952..960 } == { e<ap ? e : e+952 }, e=0..8
        int s = (t - 238) * 6;
#pragma unroll
        for (int i = 0; i < 6; ++i, ++s) {
            if (s < 108) {
                int p = s / 9;
                int e = s - 9 * p;
                int ap = (4 - (p & 3)) & 3;
                int idx = (e < ap) ? e : e + 952;
                float2 rr = rbase[idx];
                ob[PLANE * p + idx] = cA[p] * rr.x + cB[p] * rr.y;
            }
        }
    }
}

extern "C" void kernel_launch(void* const* d_in, const int* in_sizes, int n_in,
                              void* d_out, int out_size) {
    const float* x = (const float*)d_in[0];
    const float* w = (const float*)d_in[1];
    if (n_in >= 2 && in_sizes[0] == 48) {  // robustness: weights listed first
        x = (const float*)d_in[1];
        w = (const float*)d_in[0];
    }
    float* out = (float*)d_out;

    dim3 blk1(16, 16, 1);
    dim3 grd1(2, BATCH, 1);                 // 2 x 16 rows cover HO=31
    k1_invariants<<<grd1, blk1>>>(x);

    k2_expand<<<BATCH, 256>>>(w, out);
}

// round 15
// speedup vs baseline: 1.0201x; 1.0201x over previous
#include <cuda_runtime.h>
#include <math.h>

#define BATCH 512
#define HO 31
#define WO 31
#define HW 64
#define PLANE (HO * WO)          // 961
#define OUTB (12 * PLANE)        // 11532
#define RSTRIDE 962              // padded res slab stride (962*8 bytes % 16 == 0)

// Closed-form reduction (verified R1..R13):
//   per patch: S2=sum p_i^2 ; D2 signed sum (rows +,-,+,-; cols +,-,-,+)
//   dP = pairs (i, i^12) = rows 0*3 + 1*2 per column
//   out[plane] = cA[plane]*(D2/S2) + cB[plane]*(dP/S2); coefs from U3 of qubit 0.
//
// K1: horizontal-pair threads -> (Dl,dd) per patch into scratch (LDG.128 loads).
// K2: output-driven, 3 plane-groups x 512 batches; plane p's aligned float4
//     chunks start at a_p=(-p) mod 4 so 961p + a_p == 0 (mod 4): every store
//     is an aligned STG.128.

__device__ float2 g_res[BATCH * RSTRIDE];   // 3.94 MB scratch (static, allowed)

__global__ __launch_bounds__(256) void k1_invariants(const float* __restrict__ x) {
    const int t = threadIdx.x;                    // 0..15 -> patch pair (2t, 2t+1)
    const int ho = blockIdx.x * 16 + threadIdx.y;
    const int b = blockIdx.y;
    if (ho >= HO) return;
    const bool hasB = (t < 15);                   // wo=2t+1=31 doesn't exist at t=15

    // pair uses input cols 4t..4t+5 of rows 2ho..2ho+3 (LDG.128 + LDG.64, aligned)
    const float* base = x + (size_t)b * (HW * HW) + (size_t)(2 * ho) * HW + 4 * t;
    float4 a0 = *reinterpret_cast<const float4*>(base);
    float4 a1 = *reinterpret_cast<const float4*>(base + HW);
    float4 a2 = *reinterpret_cast<const float4*>(base + 2 * HW);
    float4 a3 = *reinterpret_cast<const float4*>(base + 3 * HW);
    float2 c0 = make_float2(0.f, 0.f), c1 = c0, c2 = c0, c3 = c0;
    if (hasB) {
        c0 = *reinterpret_cast<const float2*>(base + 4);
        c1 = *reinterpret_cast<const float2*>(base + HW + 4);
        c2 = *reinterpret_cast<const float2*>(base + 2 * HW + 4);
        c3 = *reinterpret_cast<const float2*>(base + 3 * HW + 4);
    }

    float2* rp = g_res + (size_t)b * RSTRIDE + ho * WO + 2 * t;

    // ---- patch A: cols (a.x, a.y, a.z, a.w) ----
    {
        float s0 = a0.x * a0.x + a0.y * a0.y + a0.z * a0.z + a0.w * a0.w;
        float s1 = a1.x * a1.x + a1.y * a1.y + a1.z * a1.z + a1.w * a1.w;
        float s2 = a2.x * a2.x + a2.y * a2.y + a2.z * a2.z + a2.w * a2.w;
        float s3 = a3.x * a3.x + a3.y * a3.y + a3.z * a3.z + a3.w * a3.w;
        float d0 = a0.x * a0.x - a0.y * a0.y - a0.z * a0.z + a0.w * a0.w;
        float d1 = a1.x * a1.x - a1.y * a1.y - a1.z * a1.z + a1.w * a1.w;
        float d2 = a2.x * a2.x - a2.y * a2.y - a2.z * a2.z + a2.w * a2.w;
        float d3 = a3.x * a3.x - a3.y * a3.y - a3.z * a3.z + a3.w * a3.w;
        float S = s0 + s1 + s2 + s3;
        float D = d0 - d1 + d2 - d3;
        float P = a0.x * a3.x + a0.y * a3.y + a0.z * a3.z + a0.w * a3.w
                + a1.x * a2.x + a1.y * a2.y + a1.z * a2.z + a1.w * a2.w;
        float inv = 1.0f / S;
        rp[0] = make_float2(D * inv, P * inv);
    }

    // ---- patch B: cols (a.z, a.w, c.x, c.y) ----
    if (hasB) {
        float s0 = a0.z * a0.z + a0.w * a0.w + c0.x * c0.x + c0.y * c0.y;
        float s1 = a1.z * a1.z + a1.w * a1.w + c1.x * c1.x + c1.y * c1.y;
        float s2 = a2.z * a2.z + a2.w * a2.w + c2.x * c2.x + c2.y * c2.y;
        float s3 = a3.z * a3.z + a3.w * a3.w + c3.x * c3.x + c3.y * c3.y;
        float d0 = a0.z * a0.z - a0.w * a0.w - c0.x * c0.x + c0.y * c0.y;
        float d1 = a1.z * a1.z - a1.w * a1.w - c1.x * c1.x + c1.y * c1.y;
        float d2 = a2.z * a2.z - a2.w * a2.w - c2.x * c2.x + c2.y * c2.y;
        float d3 = a3.z * a3.z - a3.w * a3.w - c3.x * c3.x + c3.y * c3.y;
        float S = s0 + s1 + s2 + s3;
        float D = d0 - d1 + d2 - d3;
        float P = a0.z * a3.z + a0.w * a3.w + c0.x * c3.x + c0.y * c3.y
                + a1.z * a2.z + a1.w * a2.w + c1.x * c2.x + c1.y * c2.y;
        float inv = 1.0f / S;
        rp[1] = make_float2(D * inv, P * inv);
    }
}

// grid (BATCH, 3): blockIdx.y = plane group g handles planes 4g..4g+3
__global__ __launch_bounds__(256) void k2_expand(const float* __restrict__ w,
                                                 float* __restrict__ out) {
    __shared__ float cA[12], cB[12];
    const int t = threadIdx.x;
    if (t < 4) {
        const int k = t;
        float th = w[k * 12 + 0], ph = w[k * 12 + 1], om = w[k * 12 + 2];
        float st, ct, spo, cpo, smp, cmp, sp, cp, som, com_;
        sincosf(th, &st, &ct);
        sincosf(ph, &sp, &cp);
        sincosf(ph + om, &spo, &cpo);
        sincosf(om - ph, &smp, &cmp);
        sincosf(om, &som, &com_);
        float cc = 0.5f * (1.0f + ct);
        float ss = 0.5f * (1.0f - ct);
        cA[3 * k + 0] = st * cp;                         // ex
        cB[3 * k + 0] = 2.0f * (cc * cpo - ss * cmp);
        cA[3 * k + 1] = st * sp;                         // ey
        cB[3 * k + 1] = 2.0f * (cc * spo + ss * smp);
        cA[3 * k + 2] = ct;                              // ez
        cB[3 * k + 2] = -2.0f * st * com_;
    }
    __syncthreads();

    const int b = blockIdx.x;
    const int g = blockIdx.y;                            // plane group 0..2
    const float2* rbase = g_res + (size_t)b * RSTRIDE;
    float* ob = out + (size_t)b * OUTB + (size_t)(4 * g) * PLANE;

    if (t < 238) {
        // load res[4t .. 4t+7] with 4 aligned LDG.128 (covers all shifts a_p)
        const float4* rv = reinterpret_cast<const float4*>(rbase + 4 * t);
        float4 q0 = rv[0], q1 = rv[1], q2 = rv[2], q3 = rv[3];
        float2 r[8];
        r[0] = make_float2(q0.x, q0.y); r[1] = make_float2(q0.z, q0.w);
        r[2] = make_float2(q1.x, q1.y); r[3] = make_float2(q1.z, q1.w);
        r[4] = make_float2(q2.x, q2.y); r[5] = make_float2(q2.z, q2.w);
        r[6] = make_float2(q3.x, q3.y); r[7] = make_float2(q3.z, q3.w);

#pragma unroll
        for (int pp = 0; pp < 4; ++pp) {                 // plane p = 4g + pp
            const int ap = (4 - pp) & 3;                 // (-p) mod 4, p&3 == pp
            float a = cA[4 * g + pp], gg = cB[4 * g + pp];
            float4 o;
            o.x = a * r[ap + 0].x + gg * r[ap + 0].y;
            o.y = a * r[ap + 1].x + gg * r[ap + 1].y;
            o.z = a * r[ap + 2].x + gg * r[ap + 2].y;
            o.w = a * r[ap + 3].x + gg * r[ap + 3].y;
            // 961p + ap == 0 (mod 4)  ->  aligned STG.128
            *reinterpret_cast<float4*>(ob + PLANE * pp + ap + 4 * t) = o;
        }
    } else {
        // cleanup: per plane the 9 floats not covered by fast chunks
        int s = (t - 238) * 2;                           // 2 items x 18 threads = 36
#pragma unroll
        for (int i = 0; i < 2; ++i, ++s) {
            if (s < 36) {
                int pp = s / 9;
                int e = s - 9 * pp;
                int ap = (4 - pp) & 3;
                int idx = (e < ap) ? e : e + 952;
                float2 rr = rbase[idx];
                ob[PLANE * pp + idx] = cA[4 * g + pp] * rr.x + cB[4 * g + pp] * rr.y;
            }
        }
    }
}

extern "C" void kernel_launch(void* const* d_in, const int* in_sizes, int n_in,
                              void* d_out, int out_size) {
    const float* x = (const float*)d_in[0];
    const float* w = (const float*)d_in[1];
    if (n_in >= 2 && in_sizes[0] == 48) {  // robustness: weights listed first
        x = (const float*)d_in[1];
        w = (const float*)d_in[0];
    }
    float* out = (float*)d_out;

    dim3 blk1(16, 16, 1);
    dim3 grd1(2, BATCH, 1);                 // 2 x 16 rows cover HO=31
    k1_invariants<<<grd1, blk1>>>(x);

    dim3 grd2(BATCH, 3, 1);                 // 3 plane-groups -> 3x the warps
    k2_expand<<<grd2, 256>>>(w, out);
}